// round 1
// baseline (speedup 1.0000x reference)
#include <cuda_runtime.h>

#define HDIM 10
#define MM   41
#define SMAX 512

// Repacked read-only tables (written by repack_kernel every launch; deterministic).
__device__ float4 g_W1p[SMAX * HDIM];   // [s][o] = (W1[o][0][s].re, .im, W1[o][1][s].re, .im)
__device__ float4 g_meta[SMAX];         // [s]    = (C[s].re, C[s].im, packed_idx, 0)
__device__ float4 g_W2p[MM * HDIM];     // [k][o] = (W2[o][0][k].re, .im, W2[o][1][k].re, .im)

__global__ void repack_kernel(const float2* __restrict__ W1,
                              const float2* __restrict__ W2,
                              const float2* __restrict__ C,
                              const int* __restrict__ m_idx,
                              const int* __restrict__ n_idx,
                              int S) {
    int t = blockIdx.x * blockDim.x + threadIdx.x;
    if (t < S) {
#pragma unroll
        for (int o = 0; o < HDIM; o++) {
            float2 w0 = W1[(o * 2 + 0) * S + t];
            float2 w1 = W1[(o * 2 + 1) * S + t];
            g_W1p[t * HDIM + o] = make_float4(w0.x, w0.y, w1.x, w1.y);
        }
        int m = m_idx[t], n = n_idx[t];
        const int c = MM / 2;
        int pk = (c + m) | ((c + m + n) << 8) | ((c + n) << 16);
        float2 cc = C[t];
        g_meta[t] = make_float4(cc.x, cc.y, __int_as_float(pk), 0.0f);
    }
    if (t < MM * HDIM) {
        int k = t / HDIM, o = t - k * HDIM;
        float2 w0 = W2[(o * 2 + 0) * MM + k];
        float2 w1 = W2[(o * 2 + 1) * MM + k];
        g_W2p[k * HDIM + o] = make_float4(w0.x, w0.y, w1.x, w1.y);
    }
}

// Block = 32 batch elements, 4 warps. lane == local batch element.
// Warps split the s-range (and the k-range for Bm); tree-reduce in shared.
__global__ __launch_bounds__(128, 4)
void eq_main(const float4* __restrict__ x,      // [B][41] float4 = (E0r,E0i,E1r,E1i)
             const float* __restrict__ task,    // [B][4]
             const float2* __restrict__ b1,     // [10]
             const float2* __restrict__ b2,     // [10]
             float4* __restrict__ out,          // [B]
             int S) {
    __shared__ float4 E_sh[32 * 43];            // stride 43 float4 per batch (22 KB)
    __shared__ float2 red[2][42][32];           // reduction buffers (21.5 KB)

    const int lane = threadIdx.x & 31;
    const int warp = threadIdx.x >> 5;
    const int b0 = blockIdx.x * 32;

    // Stage E for 32 batch elements (coalesced LDG.128, near-conflict-free STS).
    for (int bl = warp; bl < 32; bl += 4)
        for (int k = lane; k < MM; k += 32)
            E_sh[bl * 43 + k] = x[(size_t)(b0 + bl) * MM + k];
    __syncthreads();

    const float4* Eb = &E_sh[lane * 43];

    // ---- main s-loop: triplet features + pbc dot + W1 GEMM (main & pol-flipped) ----
    float2 accA0[HDIM], accA1[HDIM];
    float2 accP0 = make_float2(0.f, 0.f), accP1 = make_float2(0.f, 0.f);
#pragma unroll
    for (int o = 0; o < HDIM; o++) {
        accA0[o] = make_float2(0.f, 0.f);
        accA1[o] = make_float2(0.f, 0.f);
    }

    for (int s = warp; s < S; s += 4) {
        float4 meta = g_meta[s];                 // uniform across warp
        int pk = __float_as_int(meta.z);
        float4 Em  = Eb[pk & 255];               // E[c+m]   (both pols)
        float4 Emn = Eb[(pk >> 8) & 255];        // E[c+m+n]
        float4 En  = Eb[(pk >> 16) & 255];       // E[c+n]
        // Asum = sum_p E[c+m,p] * conj(E[c+m+n,p])
        float2 As;
        As.x = Em.x * Emn.x + Em.y * Emn.y + Em.z * Emn.z + Em.w * Emn.w;
        As.y = Em.y * Emn.x - Em.x * Emn.y + Em.w * Emn.z - Em.z * Emn.w;
        // F_p = Asum * E[c+n, p]
        float2 F0 = make_float2(As.x * En.x - As.y * En.y, As.x * En.y + As.y * En.x);
        float2 F1 = make_float2(As.x * En.z - As.y * En.w, As.x * En.w + As.y * En.z);
        // pbc accumulation: F_p * C[s]
        accP0.x += F0.x * meta.x - F0.y * meta.y;
        accP0.y += F0.x * meta.y + F0.y * meta.x;
        accP1.x += F1.x * meta.x - F1.y * meta.y;
        accP1.y += F1.x * meta.y + F1.y * meta.x;

        const float4* wr = &g_W1p[s * HDIM];
#pragma unroll
        for (int o = 0; o < HDIM; o++) {
            float4 w = wr[o];   // (w0.re, w0.im, w1.re, w1.im)
            accA0[o].x += w.x * F0.x - w.y * F0.y + w.z * F1.x - w.w * F1.y;
            accA0[o].y += w.x * F0.y + w.y * F0.x + w.z * F1.y + w.w * F1.x;
            accA1[o].x += w.x * F1.x - w.y * F1.y + w.z * F0.x - w.w * F0.y;
            accA1[o].y += w.x * F1.y + w.y * F1.x + w.z * F0.y + w.w * F0.x;
        }
    }

    // ---- Bm: W2 conv over k (main & pol-flipped) ----
    float2 accB0[HDIM], accB1[HDIM];
#pragma unroll
    for (int o = 0; o < HDIM; o++) {
        accB0[o] = make_float2(0.f, 0.f);
        accB1[o] = make_float2(0.f, 0.f);
    }
    for (int k = warp; k < MM; k += 4) {
        float4 Ek = Eb[k];
        const float4* wr = &g_W2p[k * HDIM];
#pragma unroll
        for (int o = 0; o < HDIM; o++) {
            float4 w = wr[o];
            accB0[o].x += w.x * Ek.x - w.y * Ek.y + w.z * Ek.z - w.w * Ek.w;
            accB0[o].y += w.x * Ek.y + w.y * Ek.x + w.z * Ek.w + w.w * Ek.z;
            accB1[o].x += w.x * Ek.z - w.y * Ek.w + w.z * Ek.x - w.w * Ek.y;
            accB1[o].y += w.x * Ek.w + w.y * Ek.z + w.z * Ek.y + w.w * Ek.x;
        }
    }

    // ---- tree reduction across the 4 warps (per lane/batch) ----
    // buffer layout: red[buf][component][lane], conflict-free
    if (warp >= 2) {
        float2* q = &red[warp - 2][0][lane];
#pragma unroll
        for (int o = 0; o < HDIM; o++) {
            q[(o) * 32]            = accA0[o];
            q[(HDIM + o) * 32]     = accA1[o];
            q[(2 * HDIM + o) * 32] = accB0[o];
            q[(3 * HDIM + o) * 32] = accB1[o];
        }
        q[40 * 32] = accP0;
        q[41 * 32] = accP1;
    }
    __syncthreads();
    if (warp < 2) {
        const float2* q = &red[warp][0][lane];
#pragma unroll
        for (int o = 0; o < HDIM; o++) {
            float2 v;
            v = q[(o) * 32];            accA0[o].x += v.x; accA0[o].y += v.y;
            v = q[(HDIM + o) * 32];     accA1[o].x += v.x; accA1[o].y += v.y;
            v = q[(2 * HDIM + o) * 32]; accB0[o].x += v.x; accB0[o].y += v.y;
            v = q[(3 * HDIM + o) * 32]; accB1[o].x += v.x; accB1[o].y += v.y;
        }
        float2 v = q[40 * 32]; accP0.x += v.x; accP0.y += v.y;
        v = q[41 * 32];        accP1.x += v.x; accP1.y += v.y;
    }
    __syncthreads();
    if (warp == 1) {
        float2* q = &red[0][0][lane];
#pragma unroll
        for (int o = 0; o < HDIM; o++) {
            q[(o) * 32]            = accA0[o];
            q[(HDIM + o) * 32]     = accA1[o];
            q[(2 * HDIM + o) * 32] = accB0[o];
            q[(3 * HDIM + o) * 32] = accB1[o];
        }
        q[40 * 32] = accP0;
        q[41 * 32] = accP1;
    }
    __syncthreads();

    if (warp == 0) {
        const float2* q = &red[0][0][lane];
#pragma unroll
        for (int o = 0; o < HDIM; o++) {
            float2 v;
            v = q[(o) * 32];            accA0[o].x += v.x; accA0[o].y += v.y;
            v = q[(HDIM + o) * 32];     accA1[o].x += v.x; accA1[o].y += v.y;
            v = q[(2 * HDIM + o) * 32]; accB0[o].x += v.x; accB0[o].y += v.y;
            v = q[(3 * HDIM + o) * 32]; accB1[o].x += v.x; accB1[o].y += v.y;
        }
        float2 v = q[40 * 32]; accP0.x += v.x; accP0.y += v.y;
        v = q[41 * 32];        accP1.x += v.x; accP1.y += v.y;

        // ---- epilogue ----
        float p = exp10f(task[(size_t)(b0 + lane) * 4] * 0.1f) * 0.5f;  // 10^(dBm/10)/NMODES
        float4 Ec = Eb[MM / 2];
        float2 o0 = make_float2(Ec.x + p * accP0.x, Ec.y + p * accP0.y);
        float2 o1 = make_float2(Ec.z + p * accP1.x, Ec.w + p * accP1.y);

        float2 t0 = make_float2(0.f, 0.f), t1 = make_float2(0.f, 0.f);
#pragma unroll
        for (int o = 0; o < HDIM; o++) {
            float2 c1 = b1[o], c2 = b2[o];
            float2 a0 = make_float2(accA0[o].x + c1.x, accA0[o].y + c1.y);
            float2 a1 = make_float2(accA1[o].x + c1.x, accA1[o].y + c1.y);
            float2 B0 = make_float2(accB0[o].x + c2.x, accB0[o].y + c2.y);
            float2 B1 = make_float2(accB1[o].x + c2.x, accB1[o].y + c2.y);
            // term += a*|b|^2 + conj(a)*b^2
            float n0 = B0.x * B0.x + B0.y * B0.y;
            float sx0 = B0.x * B0.x - B0.y * B0.y, sy0 = 2.f * B0.x * B0.y;
            t0.x += a0.x * n0 + a0.x * sx0 + a0.y * sy0;
            t0.y += a0.y * n0 + a0.x * sy0 - a0.y * sx0;
            float n1 = B1.x * B1.x + B1.y * B1.y;
            float sx1 = B1.x * B1.x - B1.y * B1.y, sy1 = 2.f * B1.x * B1.y;
            t1.x += a1.x * n1 + a1.x * sx1 + a1.y * sy1;
            t1.y += a1.y * n1 + a1.x * sy1 - a1.y * sx1;
        }
        float sc = 3.1622776601683794e-5f * p * p;   // (1e-4/sqrt(HDIM)) * P^2
        out[b0 + lane] = make_float4(o0.x + sc * t0.x, o0.y + sc * t0.y,
                                     o1.x + sc * t1.x, o1.y + sc * t1.y);
    }
}

extern "C" void kernel_launch(void* const* d_in, const int* in_sizes, int n_in,
                              void* d_out, int out_size) {
    const float4* x    = (const float4*)d_in[0];
    const float*  task = (const float*)d_in[1];
    const float2* C    = (const float2*)d_in[2];
    const float2* W1   = (const float2*)d_in[3];
    const float2* b1   = (const float2*)d_in[4];
    const float2* W2   = (const float2*)d_in[5];
    const float2* b2   = (const float2*)d_in[6];
    const int* m_idx   = (const int*)d_in[7];
    const int* n_idx   = (const int*)d_in[8];

    int S = in_sizes[8];            // number of triplets (~419)
    int B = in_sizes[1] / 4;        // batch (task_info is [B,4])

    int rtotal = (S > MM * HDIM) ? S : MM * HDIM;
    repack_kernel<<<(rtotal + 127) / 128, 128>>>(W1, W2, C, m_idx, n_idx, S);
    eq_main<<<B / 32, 128>>>(x, task, b1, b2, (float4*)d_out, S);
}

// round 2
// speedup vs baseline: 1.0866x; 1.0866x over previous
#include <cuda_runtime.h>

#define HDIM 10
#define MM   41
#define SMAX 512

typedef unsigned long long u64;

// Packed tables (written by repack_kernel each launch; deterministic).
// g_W1p[s*10 + p*2 + q] = (wx[2p], wx[2p+1], wy[2p], wy[2p+1]) for pol q
//   -> ulonglong2 load gives the two f32x2 operands directly.
__device__ float4 g_W1p[SMAX * HDIM];
__device__ float4 g_meta[SMAX];         // (Cx, Cy, -Cy, Cx) pre-arranged f32x2 pair
__device__ int    g_pk[SMAX];           // packed (c+m | c+m+n<<8 | c+n<<16)
__device__ float4 g_W2p[MM * HDIM];

__device__ __forceinline__ u64 pk2(float a, float b) {
    u64 r; asm("mov.b64 %0,{%1,%2};" : "=l"(r) : "f"(a), "f"(b)); return r;
}
__device__ __forceinline__ void up2(u64 v, float& a, float& b) {
    asm("mov.b64 {%0,%1},%2;" : "=f"(a), "=f"(b) : "l"(v));
}
__device__ __forceinline__ void fma2(u64& d, u64 a, u64 b) {
    asm("fma.rn.f32x2 %0,%1,%2,%0;" : "+l"(d) : "l"(a), "l"(b));
}
__device__ __forceinline__ void add2(u64& d, u64 a) {
    asm("add.rn.f32x2 %0,%1,%0;" : "+l"(d) : "l"(a));
}

__global__ void repack_kernel(const float2* __restrict__ W1,
                              const float2* __restrict__ W2,
                              const float2* __restrict__ C,
                              const int* __restrict__ m_idx,
                              const int* __restrict__ n_idx,
                              int S) {
    int t = blockIdx.x * blockDim.x + threadIdx.x;
    if (t < S) {
#pragma unroll
        for (int p = 0; p < 5; p++)
#pragma unroll
            for (int q = 0; q < 2; q++) {
                float2 wa = W1[((2 * p) * 2 + q) * S + t];
                float2 wb = W1[((2 * p + 1) * 2 + q) * S + t];
                g_W1p[t * 10 + p * 2 + q] = make_float4(wa.x, wb.x, wa.y, wb.y);
            }
        float2 cc = C[t];
        g_meta[t] = make_float4(cc.x, cc.y, -cc.y, cc.x);
        const int c = MM / 2;
        int m = m_idx[t], n = n_idx[t];
        g_pk[t] = (c + m) | ((c + m + n) << 8) | ((c + n) << 16);
    }
    if (t < MM) {
#pragma unroll
        for (int p = 0; p < 5; p++)
#pragma unroll
            for (int q = 0; q < 2; q++) {
                float2 wa = W2[((2 * p) * 2 + q) * MM + t];
                float2 wb = W2[((2 * p + 1) * 2 + q) * MM + t];
                g_W2p[t * 10 + p * 2 + q] = make_float4(wa.x, wb.x, wa.y, wb.y);
            }
    }
}

// Block = 32 batch elements, 4 warps; lane == local batch element.
__global__ __launch_bounds__(128, 4)
void eq_main(const float4* __restrict__ x,      // [B][41] (E0r,E0i,E1r,E1i)
             const float* __restrict__ task,    // [B][4]
             const float2* __restrict__ b1,     // [10]
             const float2* __restrict__ b2,     // [10]
             float4* __restrict__ out,          // [B]
             int S) {
    __shared__ float4 E_sh[32 * 43];            // 22 KB
    __shared__ u64 red[2][42][32];              // 21.5 KB

    const int lane = threadIdx.x & 31;
    const int warp = threadIdx.x >> 5;
    const int b0 = blockIdx.x * 32;

    for (int bl = warp; bl < 32; bl += 4)
        for (int k = lane; k < MM; k += 32)
            E_sh[bl * 43 + k] = x[(size_t)(b0 + bl) * MM + k];
    __syncthreads();

    const float4* Eb = &E_sh[lane * 43];

    // aA: [0..4]=A0x pairs, [5..9]=A0y, [10..14]=A1x, [15..19]=A1y
    u64 aA[20];
    u64 aP0 = 0ull, aP1 = 0ull;
#pragma unroll
    for (int i = 0; i < 20; i++) aA[i] = 0ull;

    for (int s = warp; s < S; s += 4) {
        const ulonglong2 mc = *(const ulonglong2*)&g_meta[s];
        const int pk = g_pk[s];
        float4 Em  = Eb[pk & 255];
        float4 Emn = Eb[(pk >> 8) & 255];
        float4 En  = Eb[(pk >> 16) & 255];
        // Asum = sum_p E[c+m,p] * conj(E[c+m+n,p])
        float Asx = Em.x * Emn.x + Em.y * Emn.y + Em.z * Emn.z + Em.w * Emn.w;
        float Asy = Em.y * Emn.x - Em.x * Emn.y + Em.w * Emn.z - Em.z * Emn.w;
        float F0x = Asx * En.x - Asy * En.y, F0y = Asx * En.y + Asy * En.x;
        float F1x = Asx * En.z - Asy * En.w, F1y = Asx * En.w + Asy * En.z;

        u64 F0xb = pk2(F0x, F0x), F0yb = pk2(F0y, F0y), F0ynb = pk2(-F0y, -F0y);
        u64 F1xb = pk2(F1x, F1x), F1yb = pk2(F1y, F1y), F1ynb = pk2(-F1y, -F1y);

        // pbc: aP += (Cx,Cy)*Fx + (-Cy,Cx)*Fy
        fma2(aP0, mc.x, F0xb); fma2(aP0, mc.y, F0yb);
        fma2(aP1, mc.x, F1xb); fma2(aP1, mc.y, F1yb);

        const ulonglong2* wr = (const ulonglong2*)&g_W1p[s * 10];
#pragma unroll
        for (int p = 0; p < 5; p++) {
            ulonglong2 u0 = wr[2 * p];      // pol0: (wx2 | wy2)
            ulonglong2 u1 = wr[2 * p + 1];  // pol1
            fma2(aA[p],      u0.x, F0xb); fma2(aA[p],      u0.y, F0ynb);
            fma2(aA[p],      u1.x, F1xb); fma2(aA[p],      u1.y, F1ynb);
            fma2(aA[5 + p],  u0.x, F0yb); fma2(aA[5 + p],  u0.y, F0xb);
            fma2(aA[5 + p],  u1.x, F1yb); fma2(aA[5 + p],  u1.y, F1xb);
            fma2(aA[10 + p], u0.x, F1xb); fma2(aA[10 + p], u0.y, F1ynb);
            fma2(aA[10 + p], u1.x, F0xb); fma2(aA[10 + p], u1.y, F0ynb);
            fma2(aA[15 + p], u0.x, F1yb); fma2(aA[15 + p], u0.y, F1xb);
            fma2(aA[15 + p], u1.x, F0yb); fma2(aA[15 + p], u1.y, F0xb);
        }
    }

    // ---- W2 conv ----
    u64 aB[20];
#pragma unroll
    for (int i = 0; i < 20; i++) aB[i] = 0ull;

    for (int k = warp; k < MM; k += 4) {
        float4 Ek = Eb[k];
        u64 E0xb = pk2(Ek.x, Ek.x), E0yb = pk2(Ek.y, Ek.y), E0ynb = pk2(-Ek.y, -Ek.y);
        u64 E1xb = pk2(Ek.z, Ek.z), E1yb = pk2(Ek.w, Ek.w), E1ynb = pk2(-Ek.w, -Ek.w);
        const ulonglong2* wr = (const ulonglong2*)&g_W2p[k * 10];
#pragma unroll
        for (int p = 0; p < 5; p++) {
            ulonglong2 u0 = wr[2 * p];
            ulonglong2 u1 = wr[2 * p + 1];
            fma2(aB[p],      u0.x, E0xb); fma2(aB[p],      u0.y, E0ynb);
            fma2(aB[p],      u1.x, E1xb); fma2(aB[p],      u1.y, E1ynb);
            fma2(aB[5 + p],  u0.x, E0yb); fma2(aB[5 + p],  u0.y, E0xb);
            fma2(aB[5 + p],  u1.x, E1yb); fma2(aB[5 + p],  u1.y, E1xb);
            fma2(aB[10 + p], u0.x, E1xb); fma2(aB[10 + p], u0.y, E1ynb);
            fma2(aB[10 + p], u1.x, E0xb); fma2(aB[10 + p], u1.y, E0ynb);
            fma2(aB[15 + p], u0.x, E1yb); fma2(aB[15 + p], u0.y, E1xb);
            fma2(aB[15 + p], u1.x, E0yb); fma2(aB[15 + p], u1.y, E0xb);
        }
    }

    // ---- 4->2->1 tree reduction across warps ----
    if (warp >= 2) {
        u64* q = &red[warp - 2][0][lane];
#pragma unroll
        for (int i = 0; i < 20; i++) { q[i * 32] = aA[i]; q[(20 + i) * 32] = aB[i]; }
        q[40 * 32] = aP0; q[41 * 32] = aP1;
    }
    __syncthreads();
    if (warp < 2) {
        const u64* q = &red[warp][0][lane];
#pragma unroll
        for (int i = 0; i < 20; i++) { add2(aA[i], q[i * 32]); add2(aB[i], q[(20 + i) * 32]); }
        add2(aP0, q[40 * 32]); add2(aP1, q[41 * 32]);
    }
    __syncthreads();
    if (warp == 1) {
        u64* q = &red[0][0][lane];
#pragma unroll
        for (int i = 0; i < 20; i++) { q[i * 32] = aA[i]; q[(20 + i) * 32] = aB[i]; }
        q[40 * 32] = aP0; q[41 * 32] = aP1;
    }
    __syncthreads();

    if (warp == 0) {
        const u64* q = &red[0][0][lane];
#pragma unroll
        for (int i = 0; i < 20; i++) { add2(aA[i], q[i * 32]); add2(aB[i], q[(20 + i) * 32]); }
        add2(aP0, q[40 * 32]); add2(aP1, q[41 * 32]);

        // unpack
        float A0x[10], A0y[10], A1x[10], A1y[10];
        float B0x[10], B0y[10], B1x[10], B1y[10];
#pragma unroll
        for (int p = 0; p < 5; p++) {
            up2(aA[p],      A0x[2 * p], A0x[2 * p + 1]);
            up2(aA[5 + p],  A0y[2 * p], A0y[2 * p + 1]);
            up2(aA[10 + p], A1x[2 * p], A1x[2 * p + 1]);
            up2(aA[15 + p], A1y[2 * p], A1y[2 * p + 1]);
            up2(aB[p],      B0x[2 * p], B0x[2 * p + 1]);
            up2(aB[5 + p],  B0y[2 * p], B0y[2 * p + 1]);
            up2(aB[10 + p], B1x[2 * p], B1x[2 * p + 1]);
            up2(aB[15 + p], B1y[2 * p], B1y[2 * p + 1]);
        }
        float P0x, P0y, P1x, P1y;
        up2(aP0, P0x, P0y);
        up2(aP1, P1x, P1y);

        float p = exp10f(task[(size_t)(b0 + lane) * 4] * 0.1f) * 0.5f;
        float4 Ec = Eb[MM / 2];
        float o0x = Ec.x + p * P0x, o0y = Ec.y + p * P0y;
        float o1x = Ec.z + p * P1x, o1y = Ec.w + p * P1y;

        float t0x = 0.f, t0y = 0.f, t1x = 0.f, t1y = 0.f;
#pragma unroll
        for (int o = 0; o < HDIM; o++) {
            float2 c1 = b1[o], c2 = b2[o];
            float a0x = A0x[o] + c1.x, a0y = A0y[o] + c1.y;
            float a1x = A1x[o] + c1.x, a1y = A1y[o] + c1.y;
            float bx0 = B0x[o] + c2.x, by0 = B0y[o] + c2.y;
            float bx1 = B1x[o] + c2.x, by1 = B1y[o] + c2.y;
            float n0 = bx0 * bx0 + by0 * by0;
            float sx0 = bx0 * bx0 - by0 * by0, sy0 = 2.f * bx0 * by0;
            t0x += a0x * n0 + a0x * sx0 + a0y * sy0;
            t0y += a0y * n0 + a0x * sy0 - a0y * sx0;
            float n1 = bx1 * bx1 + by1 * by1;
            float sx1 = bx1 * bx1 - by1 * by1, sy1 = 2.f * bx1 * by1;
            t1x += a1x * n1 + a1x * sx1 + a1y * sy1;
            t1y += a1y * n1 + a1x * sy1 - a1y * sx1;
        }
        float sc = 3.1622776601683794e-5f * p * p;   // (1e-4/sqrt(HDIM)) * P^2
        out[b0 + lane] = make_float4(o0x + sc * t0x, o0y + sc * t0y,
                                     o1x + sc * t1x, o1y + sc * t1y);
    }
}

extern "C" void kernel_launch(void* const* d_in, const int* in_sizes, int n_in,
                              void* d_out, int out_size) {
    const float4* x    = (const float4*)d_in[0];
    const float*  task = (const float*)d_in[1];
    const float2* C    = (const float2*)d_in[2];
    const float2* W1   = (const float2*)d_in[3];
    const float2* b1   = (const float2*)d_in[4];
    const float2* W2   = (const float2*)d_in[5];
    const float2* b2   = (const float2*)d_in[6];
    const int* m_idx   = (const int*)d_in[7];
    const int* n_idx   = (const int*)d_in[8];

    int S = in_sizes[8];
    int B = in_sizes[1] / 4;

    repack_kernel<<<(S + 127) / 128, 128>>>(W1, W2, C, m_idx, n_idx, S);
    eq_main<<<B / 32, 128>>>(x, task, b1, b2, (float4*)d_out, S);
}